// round 9
// baseline (speedup 1.0000x reference)
#include <cuda_runtime.h>
#include <cuda_fp16.h>

// Shapes
#define BB   2
#define HH   160
#define WW   160
#define DD   96
#define HOUT 154
#define WOUT 154
#define DOUT 90
#define CHST (160*160*96)          // x channel stride (elements)
#define Y_ELEMS (BB*HH*WW*DD)      // 4,915,200

// Fused tiling
#define WOCF 8                     // w outputs per block (last chunk: 2)
#define WICF (WOCF+6)              // 14 input w-lines
#define SEGH 22                    // h outputs per block (154 = 7*22)
#define NHSEG 7
#define NWCH 20                    // ceil(154/8)
#define TPB  384
#define TOTB (NWCH*NHSEG*BB)       // 280
#define PMAX (WOCF*90)             // 720 positions per block
#define EMAX (WICF*96)             // 1344
#define LMAX (WICF*90)             // 1260

// smem byte offsets
#define OFF_EA   0                  // uint2[1344]  A half4 expanded
#define OFF_EB   10752              // uint2[1344]
#define OFF_EN   21504              // u32 [1344]
#define OFF_LSA  26880              // uint2[1260]  D-window line sums
#define OFF_LSB  36960
#define OFF_LSN  47040              // u32 [1260]
#define OFF_RA   52080              // uint2[7*720] ring of W-window sums
#define OFF_RB   92400
#define OFF_RN   132720             // u32 [7*720]
#define SMEMF    152880

__device__ double   g_acc;          // zero-init at load; reset by last block
__device__ unsigned g_done;

__device__ __forceinline__ __half2 u2h(unsigned u) { return *reinterpret_cast<__half2*>(&u); }
__device__ __forceinline__ unsigned h2u(__half2 h) { return *reinterpret_cast<unsigned*>(&h); }

__device__ __forceinline__ void nd_class(float A, float B, float Nf,
                                         float& num, float& den)
{
    const float inv343 = 1.0f / 343.0f;
    const float K2C = 49.0f / 48.0f;
    const float K4C = K2C * K2C;
    const float Cc  = 0.00045f;            // (0.03*1)^2/2
    float yb  = Nf * inv343;
    float g1  = 1.0f - yb;
    float Ab  = A * inv343;
    float Bb  = B * inv343;
    num = fmaf(K2C * Ab, g1, Cc);
    float var = fmaf(-Ab, Ab, Bb);
    den = fmaf((K4C * var) * yb, g1, Cc);
}

__global__ __launch_bounds__(TPB) void kf(const float* __restrict__ X,
                                          const int* __restrict__ Y,
                                          float* __restrict__ out)
{
    extern __shared__ char sm[];
    uint2*    ea  = (uint2*)(sm + OFF_EA);
    uint2*    eb  = (uint2*)(sm + OFF_EB);
    unsigned* en  = (unsigned*)(sm + OFF_EN);
    uint2*    lsA = (uint2*)(sm + OFF_LSA);
    uint2*    lsB = (uint2*)(sm + OFF_LSB);
    unsigned* lsN = (unsigned*)(sm + OFF_LSN);
    uint2*    rA  = (uint2*)(sm + OFF_RA);
    uint2*    rB  = (uint2*)(sm + OFF_RB);
    unsigned* rN  = (unsigned*)(sm + OFF_RN);

    const int tid = threadIdx.x;
    const int wb  = blockIdx.x * WOCF;
    const int woc = min(WOCF, WOUT - wb);
    const int wic = woc + 6;
    const int h0  = blockIdx.y * SEGH;
    const int b   = blockIdx.z;
    const int P   = woc * 90;

    // ---- y dtype probe (int64 -> odd 32-bit words all zero) ----
    __shared__ int s_ys;
    if (tid == 0) s_ys = 2;
    __syncthreads();
    if (tid < 128) { if (Y[2 * tid + 1] != 0) s_ys = 1; }
    __syncthreads();
    const int ys = s_ys;

    const float* Xb = X + (size_t)b * 4 * CHST;
    const int*   Yb = Y + (size_t)ys * (size_t)b * (HH * WW * DD);

    // sliding-H accumulators: 2 fixed positions per thread (p = tid, tid+TPB)
    float4 aA0 = make_float4(0.f,0.f,0.f,0.f), aA1 = aA0;
    float4 aB0 = aA0, aB1 = aA0;
    unsigned s02a = 0u, s13a = 0u, s02b = 0u, s13b = 0u;
    float lsum = 0.f;

    const int nA = wic * 96;
    const int nB = wic * 45;
    const __half2 hz = u2h(0u);

    for (int hh = 0; hh < SEGH + 6; ++hh) {
        const int h = h0 + hh;

        // ---- Stage A: a = sigmoid(x[y]) - 0.5, expand per-class half4 ----
        const float* Xl = Xb + (size_t)h * (WW * DD);
        const int*   Yl = Yb + (size_t)ys * (size_t)h * (WW * DD);
        for (int i = tid; i < nA; i += TPB) {
            int wl = i / 96;
            int d  = i - wl * 96;
            int off = (wb + wl) * 96 + d;
            int k = Yl[off * ys];
            float x0 = Xl[off];
            float x1 = Xl[off + CHST];
            float x2 = Xl[off + 2 * CHST];
            float x3 = Xl[off + 3 * CHST];
            float v = (k == 0) ? x0 : (k == 1) ? x1 : (k == 2) ? x2 : x3;
            float t = __fdividef(1.0f, 1.0f + __expf(-v));
            float a = t - 0.5f;
            unsigned ha = (unsigned)__half_as_ushort(__float2half_rn(a));
            unsigned hb = (unsigned)__half_as_ushort(__float2half_rn(a * a));
            int sh = (k & 1) ? 16 : 0;
            unsigned sa = ha << sh, sbv = hb << sh;
            bool hi = (k & 2) != 0;
            ea[i] = make_uint2(hi ? 0u : sa,  hi ? sa  : 0u);
            eb[i] = make_uint2(hi ? 0u : sbv, hi ? sbv : 0u);
            en[i] = 1u << (k * 8);
        }
        __syncthreads();

        // ---- Stage B: D-window-7, paired (2 outputs share 6-tap core) ----
        for (int j = tid; j < nB; j += TPB) {
            int wl = j / 45;
            int de = (j - wl * 45) * 2;
            int base = wl * 96 + de;
            __half2 A01 = hz, A23 = hz, B01 = hz, B23 = hz;
            unsigned n = 0u;
            #pragma unroll
            for (int t7 = 1; t7 < 7; ++t7) {
                uint2 ua = ea[base + t7];
                uint2 ub = eb[base + t7];
                A01 = __hadd2(A01, u2h(ua.x)); A23 = __hadd2(A23, u2h(ua.y));
                B01 = __hadd2(B01, u2h(ub.x)); B23 = __hadd2(B23, u2h(ub.y));
                n += en[base + t7];
            }
            uint2 ua0 = ea[base],     ub0 = eb[base];
            uint2 ua7 = ea[base + 7], ub7 = eb[base + 7];
            unsigned n0 = en[base], n7 = en[base + 7];
            int o = wl * 90 + de;
            lsA[o]   = make_uint2(h2u(__hadd2(A01, u2h(ua0.x))), h2u(__hadd2(A23, u2h(ua0.y))));
            lsB[o]   = make_uint2(h2u(__hadd2(B01, u2h(ub0.x))), h2u(__hadd2(B23, u2h(ub0.y))));
            lsN[o]   = n + n0;
            lsA[o+1] = make_uint2(h2u(__hadd2(A01, u2h(ua7.x))), h2u(__hadd2(A23, u2h(ua7.y))));
            lsB[o+1] = make_uint2(h2u(__hadd2(B01, u2h(ub7.x))), h2u(__hadd2(B23, u2h(ub7.y))));
            lsN[o+1] = n + n7;
        }
        __syncthreads();

        // ---- Stage C: W-window-7 + sliding-H update + finalize ----
        const int rs = hh % 7;
        #pragma unroll
        for (int s = 0; s < 2; ++s) {
            int p = tid + s * TPB;
            if (p < P) {
                int wl = p / 90;
                int dd = p - wl * 90;
                __half2 A01 = hz, A23 = hz, B01 = hz, B23 = hz;
                unsigned n = 0u;
                #pragma unroll
                for (int j7 = 0; j7 < 7; ++j7) {
                    int q = (wl + j7) * 90 + dd;
                    uint2 ua = lsA[q], ub = lsB[q];
                    A01 = __hadd2(A01, u2h(ua.x)); A23 = __hadd2(A23, u2h(ua.y));
                    B01 = __hadd2(B01, u2h(ub.x)); B23 = __hadd2(B23, u2h(ub.y));
                    n += lsN[q];
                }
                float2 fa01 = __half22float2(A01), fa23 = __half22float2(A23);
                float2 fb01 = __half22float2(B01), fb23 = __half22float2(B23);
                float4& aA = s ? aA1 : aA0;
                float4& aB = s ? aB1 : aB0;
                unsigned& s02 = s ? s02b : s02a;
                unsigned& s13 = s ? s13b : s13a;

                aA.x += fa01.x; aA.y += fa01.y; aA.z += fa23.x; aA.w += fa23.y;
                aB.x += fb01.x; aB.y += fb01.y; aB.z += fb23.x; aB.w += fb23.y;
                s02 += n & 0x00FF00FFu;
                s13 += (n >> 8) & 0x00FF00FFu;

                int rp = rs * PMAX + p;
                if (hh >= 7) {
                    uint2 oa = rA[rp], ob = rB[rp];
                    unsigned on = rN[rp];
                    float2 c01 = __half22float2(u2h(oa.x)), c23 = __half22float2(u2h(oa.y));
                    float2 d01 = __half22float2(u2h(ob.x)), d23 = __half22float2(u2h(ob.y));
                    aA.x -= c01.x; aA.y -= c01.y; aA.z -= c23.x; aA.w -= c23.y;
                    aB.x -= d01.x; aB.y -= d01.y; aB.z -= d23.x; aB.w -= d23.y;
                    s02 -= on & 0x00FF00FFu;
                    s13 -= (on >> 8) & 0x00FF00FFu;
                }
                rA[rp] = make_uint2(h2u(A01), h2u(A23));
                rB[rp] = make_uint2(h2u(B01), h2u(B23));
                rN[rp] = n;

                if (hh >= 6) {
                    float N0 = (float)(s02 & 0xFFFFu);
                    float N2 = (float)(s02 >> 16);
                    float N1 = (float)(s13 & 0xFFFFu);
                    float N3 = (float)(s13 >> 16);
                    float n0, d0, n1, d1, n2, d2, n3, d3;
                    nd_class(aA.x, aB.x, N0, n0, d0);
                    nd_class(aA.y, aB.y, N1, n1, d1);
                    nd_class(aA.z, aB.z, N2, n2, d2);
                    nd_class(aA.w, aB.w, N3, n3, d3);
                    float p01 = d0 * d1, p23 = d2 * d3;
                    float num = fmaf(n0, d1, n1 * d0) * p23 + fmaf(n2, d3, n3 * d2) * p01;
                    lsum += __fdividef(num, p01 * p23);
                }
            }
        }
        __syncthreads();
    }

    // ---- block reduce + global accumulate + last-block finalize ----
    float* red = (float*)sm;
    red[tid] = lsum;
    __syncthreads();
    if (tid < 128) red[tid] += red[tid + 128] + red[tid + 256];
    __syncthreads();
    if (tid < 64) red[tid] += red[tid + 64];
    __syncthreads();
    if (tid < 32) {
        float v = red[tid] + red[tid + 32];
        #pragma unroll
        for (int o = 16; o > 0; o >>= 1)
            v += __shfl_down_sync(0xffffffffu, v, o);
        if (tid == 0) {
            atomicAdd(&g_acc, (double)v);
            __threadfence();
            unsigned t = atomicAdd(&g_done, 1u);
            if (t == TOTB - 1) {
                double tot = g_acc;
                out[0] = (float)(1.0 - tot * (1.0 / 17075520.0));
                __threadfence();
                g_acc = 0.0;
                g_done = 0u;
            }
        }
    }
}

extern "C" void kernel_launch(void* const* d_in, const int* in_sizes, int n_in,
                              void* d_out, int out_size)
{
    (void)out_size;
    const float* X;
    const int*   Y;
    if (n_in >= 2 && in_sizes[0] == Y_ELEMS) {
        Y = (const int*)d_in[0];
        X = (const float*)d_in[1];
    } else {
        X = (const float*)d_in[0];
        Y = (const int*)d_in[1];
    }

    static int smem_set = 0;
    if (!smem_set) {
        cudaFuncSetAttribute(kf, cudaFuncAttributeMaxDynamicSharedMemorySize, SMEMF);
        smem_set = 1;
    }

    kf<<<dim3(NWCH, NHSEG, BB), TPB, SMEMF>>>(X, Y, (float*)d_out);
}

// round 10
// speedup vs baseline: 1.2815x; 1.2815x over previous
#include <cuda_runtime.h>
#include <cuda_fp16.h>

// Shapes
#define BB   2
#define HH   160
#define WW   160
#define DD   96
#define WOUT 154
#define CHST (160*160*96)          // x channel stride (elements)
#define Y_ELEMS (BB*HH*WW*DD)      // 4,915,200

// Fused tiling: blocks tile (w-chunk x h-seg x (b, d-half))
#define WOCF 8                     // w outputs per block (last chunk: 2)
#define WICF (WOCF+6)
#define SEGH 22                    // h outputs per block (154 = 7*22)
#define NHSEG 7
#define NWCH 20
#define TPB  384
#define TOTB (NWCH*NHSEG*BB*2)     // 560
#define PMAX (WOCF*45)             // 360 positions per block
#define DIN  52                    // input d per half
#define DLN  46                    // D-window line outputs per half

// smem byte offsets (total 75,664 B -> 3 CTAs/SM)
#define OFF_EA   0                  // uint2[14*52]  A half4 expanded
#define OFF_EB   5824               // uint2[14*52]
#define OFF_EN   11648              // u8  [14*52]   class id
#define OFF_LSA  12384              // uint2[14*46]  D-window line sums
#define OFF_LSB  17536
#define OFF_LSN  22688              // u32 [14*46]
#define OFF_RA   25264              // uint2[7*360]  ring of W-window sums
#define OFF_RB   45424
#define OFF_RN   65584              // u32 [7*360]
#define SMEMF    75664

__device__ double   g_acc;          // zero-init at load; reset by last block
__device__ unsigned g_done;

__device__ __forceinline__ __half2 u2h(unsigned u) { return *reinterpret_cast<__half2*>(&u); }
__device__ __forceinline__ unsigned h2u(__half2 h) { return *reinterpret_cast<unsigned*>(&h); }

__device__ __forceinline__ void nd_class(float A, float B, float Nf,
                                         float& num, float& den)
{
    const float inv343 = 1.0f / 343.0f;
    const float K2C = 49.0f / 48.0f;
    const float K4C = K2C * K2C;
    const float Cc  = 0.00045f;            // (0.03*1)^2/2
    float yb  = Nf * inv343;
    float g1  = 1.0f - yb;
    float Ab  = A * inv343;
    float Bb  = B * inv343;
    num = fmaf(K2C * Ab, g1, Cc);
    float var = fmaf(-Ab, Ab, Bb);
    den = fmaf((K4C * var) * yb, g1, Cc);
}

__global__ __launch_bounds__(TPB, 3) void kf(const float* __restrict__ X,
                                             const int* __restrict__ Y,
                                             float* __restrict__ out)
{
    extern __shared__ char sm[];
    uint2*         ea  = (uint2*)(sm + OFF_EA);
    uint2*         eb  = (uint2*)(sm + OFF_EB);
    unsigned char* en  = (unsigned char*)(sm + OFF_EN);
    uint2*         lsA = (uint2*)(sm + OFF_LSA);
    uint2*         lsB = (uint2*)(sm + OFF_LSB);
    unsigned*      lsN = (unsigned*)(sm + OFF_LSN);
    uint2*         rA  = (uint2*)(sm + OFF_RA);
    uint2*         rB  = (uint2*)(sm + OFF_RB);
    unsigned*      rN  = (unsigned*)(sm + OFF_RN);

    const int tid = threadIdx.x;
    const int wb  = blockIdx.x * WOCF;
    const int woc = min(WOCF, WOUT - wb);
    const int wic = woc + 6;
    const int h0  = blockIdx.y * SEGH;
    const int b   = blockIdx.z >> 1;
    const int gHalf = blockIdx.z & 1;      // d-half: 0 -> outputs 0..44, 1 -> 45..89
    const int d0  = gHalf * 44;            // input d base (52 inputs)
    const int u0  = gHalf;                 // local line-output offset
    const int P   = woc * 45;

    // ---- y dtype probe (int64 -> odd 32-bit words all zero) ----
    __shared__ int s_ys;
    if (tid == 0) s_ys = 2;
    __syncthreads();
    if (tid < 128) { if (Y[2 * tid + 1] != 0) s_ys = 1; }
    __syncthreads();
    const int ys = s_ys;

    const float* Xb = X + (size_t)b * 4 * CHST;
    const int*   Yb = Y + (size_t)ys * (size_t)b * (HH * WW * DD);

    // sliding-H accumulators: one fixed position per thread
    float4 aA = make_float4(0.f, 0.f, 0.f, 0.f);
    float4 aB = aA;
    unsigned s02 = 0u, s13 = 0u;
    float lsum = 0.f;

    const int nA = wic * DIN;
    const int nB = wic * 23;               // D-output pairs per line set
    const __half2 hz = u2h(0u);

    const int pw = (tid < P) ? (tid / 45) : 0;
    const int pd = (tid < P) ? (tid - pw * 45) : 0;
    const int lidx = pd + u0;

    for (int hh = 0; hh < SEGH + 6; ++hh) {
        const int h = h0 + hh;

        // ---- Stage A: a = sigmoid(x[y]) - 0.5, expand per-class half4 ----
        const float* Xl = Xb + (size_t)h * (WW * DD);
        const int*   Yl = Yb + (size_t)ys * (size_t)h * (WW * DD);
        for (int i = tid; i < nA; i += TPB) {
            int wl = i / DIN;
            int dl = i - wl * DIN;
            int off = (wb + wl) * 96 + d0 + dl;
            int k = Yl[off * ys];
            float x0 = Xl[off];
            float x1 = Xl[off + CHST];
            float x2 = Xl[off + 2 * CHST];
            float x3 = Xl[off + 3 * CHST];
            float v = (k == 0) ? x0 : (k == 1) ? x1 : (k == 2) ? x2 : x3;
            float t = __fdividef(1.0f, 1.0f + __expf(-v));
            float a = t - 0.5f;
            unsigned ha = (unsigned)__half_as_ushort(__float2half_rn(a));
            unsigned hb = (unsigned)__half_as_ushort(__float2half_rn(a * a));
            int sh = (k & 1) ? 16 : 0;
            unsigned sa = ha << sh, sbv = hb << sh;
            bool hi = (k & 2) != 0;
            ea[i] = make_uint2(hi ? 0u : sa,  hi ? sa  : 0u);
            eb[i] = make_uint2(hi ? 0u : sbv, hi ? sbv : 0u);
            en[i] = (unsigned char)k;
        }
        __syncthreads();

        // ---- Stage B: D-window-7, paired (2 outputs share 6-tap core) ----
        for (int j = tid; j < nB; j += TPB) {
            int wl = j / 23;
            int de = (j - wl * 23) * 2;
            int base = wl * DIN + de;
            __half2 A01 = hz, A23 = hz, B01 = hz, B23 = hz;
            unsigned n = 0u;
            #pragma unroll
            for (int t7 = 1; t7 < 7; ++t7) {
                uint2 ua = ea[base + t7];
                uint2 ub = eb[base + t7];
                A01 = __hadd2(A01, u2h(ua.x)); A23 = __hadd2(A23, u2h(ua.y));
                B01 = __hadd2(B01, u2h(ub.x)); B23 = __hadd2(B23, u2h(ub.y));
                n += 1u << (en[base + t7] * 8);
            }
            uint2 ua0 = ea[base],     ub0 = eb[base];
            uint2 ua7 = ea[base + 7], ub7 = eb[base + 7];
            unsigned n0 = 1u << (en[base] * 8);
            unsigned n7 = 1u << (en[base + 7] * 8);
            int o = wl * DLN + de;
            lsA[o]   = make_uint2(h2u(__hadd2(A01, u2h(ua0.x))), h2u(__hadd2(A23, u2h(ua0.y))));
            lsB[o]   = make_uint2(h2u(__hadd2(B01, u2h(ub0.x))), h2u(__hadd2(B23, u2h(ub0.y))));
            lsN[o]   = n + n0;
            lsA[o+1] = make_uint2(h2u(__hadd2(A01, u2h(ua7.x))), h2u(__hadd2(A23, u2h(ua7.y))));
            lsB[o+1] = make_uint2(h2u(__hadd2(B01, u2h(ub7.x))), h2u(__hadd2(B23, u2h(ub7.y))));
            lsN[o+1] = n + n7;
        }
        __syncthreads();

        // ---- Stage C: W-window-7 + sliding-H update + finalize ----
        if (tid < P) {
            __half2 A01 = hz, A23 = hz, B01 = hz, B23 = hz;
            unsigned n = 0u;
            #pragma unroll
            for (int j7 = 0; j7 < 7; ++j7) {
                int q = (pw + j7) * DLN + lidx;
                uint2 ua = lsA[q], ub = lsB[q];
                A01 = __hadd2(A01, u2h(ua.x)); A23 = __hadd2(A23, u2h(ua.y));
                B01 = __hadd2(B01, u2h(ub.x)); B23 = __hadd2(B23, u2h(ub.y));
                n += lsN[q];
            }
            float2 fa01 = __half22float2(A01), fa23 = __half22float2(A23);
            float2 fb01 = __half22float2(B01), fb23 = __half22float2(B23);

            aA.x += fa01.x; aA.y += fa01.y; aA.z += fa23.x; aA.w += fa23.y;
            aB.x += fb01.x; aB.y += fb01.y; aB.z += fb23.x; aB.w += fb23.y;
            s02 += n & 0x00FF00FFu;
            s13 += (n >> 8) & 0x00FF00FFu;

            int rp = (hh % 7) * PMAX + tid;
            if (hh >= 7) {
                uint2 oa = rA[rp], ob = rB[rp];
                unsigned on = rN[rp];
                float2 c01 = __half22float2(u2h(oa.x)), c23 = __half22float2(u2h(oa.y));
                float2 d01 = __half22float2(u2h(ob.x)), d23 = __half22float2(u2h(ob.y));
                aA.x -= c01.x; aA.y -= c01.y; aA.z -= c23.x; aA.w -= c23.y;
                aB.x -= d01.x; aB.y -= d01.y; aB.z -= d23.x; aB.w -= d23.y;
                s02 -= on & 0x00FF00FFu;
                s13 -= (on >> 8) & 0x00FF00FFu;
            }
            rA[rp] = make_uint2(h2u(A01), h2u(A23));
            rB[rp] = make_uint2(h2u(B01), h2u(B23));
            rN[rp] = n;

            if (hh >= 6) {
                float N0 = (float)(s02 & 0xFFFFu);
                float N2 = (float)(s02 >> 16);
                float N1 = (float)(s13 & 0xFFFFu);
                float N3 = (float)(s13 >> 16);
                float n0, d0c, n1, d1, n2, d2, n3, d3;
                nd_class(aA.x, aB.x, N0, n0, d0c);
                nd_class(aA.y, aB.y, N1, n1, d1);
                nd_class(aA.z, aB.z, N2, n2, d2);
                nd_class(aA.w, aB.w, N3, n3, d3);
                float p01 = d0c * d1, p23 = d2 * d3;
                float num = fmaf(n0, d1, n1 * d0c) * p23 + fmaf(n2, d3, n3 * d2) * p01;
                lsum += __fdividef(num, p01 * p23);
            }
        }
        __syncthreads();
    }

    // ---- block reduce + global accumulate + last-block finalize ----
    float* red = (float*)sm;
    red[tid] = lsum;
    __syncthreads();
    if (tid < 128) red[tid] += red[tid + 128] + red[tid + 256];
    __syncthreads();
    if (tid < 64) red[tid] += red[tid + 64];
    __syncthreads();
    if (tid < 32) {
        float v = red[tid] + red[tid + 32];
        #pragma unroll
        for (int o = 16; o > 0; o >>= 1)
            v += __shfl_down_sync(0xffffffffu, v, o);
        if (tid == 0) {
            atomicAdd(&g_acc, (double)v);
            __threadfence();
            unsigned t = atomicAdd(&g_done, 1u);
            if (t == TOTB - 1) {
                double tot = g_acc;
                out[0] = (float)(1.0 - tot * (1.0 / 17075520.0));
                __threadfence();
                g_acc = 0.0;
                g_done = 0u;
            }
        }
    }
}

extern "C" void kernel_launch(void* const* d_in, const int* in_sizes, int n_in,
                              void* d_out, int out_size)
{
    (void)out_size;
    const float* X;
    const int*   Y;
    if (n_in >= 2 && in_sizes[0] == Y_ELEMS) {
        Y = (const int*)d_in[0];
        X = (const float*)d_in[1];
    } else {
        X = (const float*)d_in[0];
        Y = (const int*)d_in[1];
    }

    static int smem_set = 0;
    if (!smem_set) {
        cudaFuncSetAttribute(kf, cudaFuncAttributeMaxDynamicSharedMemorySize, SMEMF);
        smem_set = 1;
    }

    kf<<<dim3(NWCH, NHSEG, BB * 2), TPB, SMEMF>>>(X, Y, (float*)d_out);
}

// round 11
// speedup vs baseline: 1.7488x; 1.3646x over previous
#include <cuda_runtime.h>
#include <cuda_fp16.h>

// Shapes
#define BB   2
#define HH   160
#define WW   160
#define DD   96
#define WOUT 154
#define CHST (160*160*96)          // x channel stride (elements)
#define Y_ELEMS (BB*HH*WW*DD)      // 4,915,200

// Fused tiling: blocks tile (w-chunk x h-seg x (b, d-half))
#define WOCF 8                     // w outputs per block (last chunk: 2)
#define SEGH 22                    // h outputs per block (154 = 7*22)
#define NHSEG 7
#define NWCH 20
#define TPB  384
#define TOTB (NWCH*NHSEG*BB*2)     // 560
#define PMAX (WOCF*45)             // 360 positions per block
#define DIN  52                    // input d per half
#define DLN  46                    // D-window line outputs per half
#define NITER (SEGH+6)             // 28

// smem byte offsets (total 75,664 B -> 3 CTAs/SM)
#define OFF_EAB  0                  // uint4[14*52]  {A01,A23,B01,B23} half4x2
#define OFF_EN   11648              // u8  [14*52]   class id
#define OFF_LSAB 12384              // uint4[14*46]  D-window line sums
#define OFF_LSN  22688              // u32 [14*46]
#define OFF_RAB  25264              // uint4[7*360]  ring of W-window sums
#define OFF_RN   65584              // u32 [7*360]
#define SMEMF    75664

__device__ double   g_acc;          // zero-init at load; reset by last block
__device__ unsigned g_done;

__device__ __forceinline__ __half2 u2h(unsigned u) { return *reinterpret_cast<__half2*>(&u); }
__device__ __forceinline__ unsigned h2u(__half2 h) { return *reinterpret_cast<unsigned*>(&h); }

__device__ __forceinline__ void nd_class(float A, float B, float Nf,
                                         float& num, float& den)
{
    const float inv343 = 1.0f / 343.0f;
    const float K2C = 49.0f / 48.0f;
    const float K4C = K2C * K2C;
    const float Cc  = 0.00045f;            // (0.03*1)^2/2
    float yb  = Nf * inv343;
    float g1  = 1.0f - yb;
    float Ab  = A * inv343;
    float Bb  = B * inv343;
    num = fmaf(K2C * Ab, g1, Cc);
    float var = fmaf(-Ab, Ab, Bb);
    den = fmaf((K4C * var) * yb, g1, Cc);
}

__global__ __launch_bounds__(TPB, 3) void kf(const float* __restrict__ X,
                                             const int* __restrict__ Y,
                                             float* __restrict__ out)
{
    extern __shared__ char sm[];
    uint4*         eab  = (uint4*)(sm + OFF_EAB);
    unsigned char* en   = (unsigned char*)(sm + OFF_EN);
    uint4*         lsAB = (uint4*)(sm + OFF_LSAB);
    unsigned*      lsN  = (unsigned*)(sm + OFF_LSN);
    uint4*         rAB  = (uint4*)(sm + OFF_RAB);
    unsigned*      rN   = (unsigned*)(sm + OFF_RN);

    const int tid = threadIdx.x;
    const int wb  = blockIdx.x * WOCF;
    const int woc = min(WOCF, WOUT - wb);
    const int wic = woc + 6;
    const int h0  = blockIdx.y * SEGH;
    const int b   = blockIdx.z >> 1;
    const int gHalf = blockIdx.z & 1;      // d-half: 0 -> outputs 0..44, 1 -> 45..89
    const int d0  = gHalf * 44;            // input d base (52 inputs)
    const int u0  = gHalf;                 // local line-output offset
    const int P   = woc * 45;

    // ---- y dtype probe (int64 -> odd 32-bit words all zero) ----
    __shared__ int s_ys;
    if (tid == 0) s_ys = 2;
    __syncthreads();
    if (tid < 128) { if (Y[2 * tid + 1] != 0) s_ys = 1; }
    __syncthreads();
    const int ys = s_ys;

    const float* Xb = X + (size_t)b * 4 * CHST;
    const int*   Yb = Y + (size_t)ys * (size_t)b * (HH * WW * DD);

    const int nA = wic * DIN;

    // precomputed voxel offsets for the (up to) 2 stage-A elements this thread owns
    int off0 = 0, off1 = 0;
    const bool hasA0 = (tid < nA);
    const bool hasA1 = (tid + TPB < nA);
    if (hasA0) { int wl = tid / DIN, dl = tid - wl * DIN; off0 = (wb + wl) * 96 + d0 + dl; }
    if (hasA1) { int i1 = tid + TPB; int wl = i1 / DIN, dl = i1 - wl * DIN; off1 = (wb + wl) * 96 + d0 + dl; }

    // sliding-H accumulators: one fixed position per thread
    float4 aA = make_float4(0.f, 0.f, 0.f, 0.f);
    float4 aB = aA;
    unsigned s02 = 0u, s13 = 0u;
    float lsum = 0.f;

    const int nB = wic * 23;               // D-output pairs
    const __half2 hz = u2h(0u);

    const int pw = (tid < P) ? (tid / 45) : 0;
    const int pd = (tid < P) ? (tid - pw * 45) : 0;
    const int lidx = pd + u0;

    // ---- prefetch row 0: y then x[y] only ----
    int   pk0 = 0, pk1 = 0;
    float pv0 = 0.f, pv1 = 0.f;
    {
        const float* Xl = Xb + (size_t)h0 * (WW * DD);
        const int*   Yl = Yb + (size_t)ys * (size_t)h0 * (WW * DD);
        if (hasA0) { pk0 = Yl[off0 * ys]; pv0 = Xl[off0 + pk0 * CHST]; }
        if (hasA1) { pk1 = Yl[off1 * ys]; pv1 = Xl[off1 + pk1 * CHST]; }
    }

    for (int hh = 0; hh < NITER; ++hh) {
        // ---- Stage A: convert prefetched values, store expanded half4x2 ----
        if (hasA0) {
            float t = __fdividef(1.0f, 1.0f + __expf(-pv0));
            float a = t - 0.5f;
            unsigned ha = (unsigned)__half_as_ushort(__float2half_rn(a));
            unsigned hb = (unsigned)__half_as_ushort(__float2half_rn(a * a));
            int sh = (pk0 & 1) ? 16 : 0;
            unsigned sa = ha << sh, sbv = hb << sh;
            bool hi = (pk0 & 2) != 0;
            eab[tid] = make_uint4(hi ? 0u : sa,  hi ? sa  : 0u,
                                  hi ? 0u : sbv, hi ? sbv : 0u);
            en[tid] = (unsigned char)pk0;
        }
        if (hasA1) {
            float t = __fdividef(1.0f, 1.0f + __expf(-pv1));
            float a = t - 0.5f;
            unsigned ha = (unsigned)__half_as_ushort(__float2half_rn(a));
            unsigned hb = (unsigned)__half_as_ushort(__float2half_rn(a * a));
            int sh = (pk1 & 1) ? 16 : 0;
            unsigned sa = ha << sh, sbv = hb << sh;
            bool hi = (pk1 & 2) != 0;
            eab[tid + TPB] = make_uint4(hi ? 0u : sa,  hi ? sa  : 0u,
                                        hi ? 0u : sbv, hi ? sbv : 0u);
            en[tid + TPB] = (unsigned char)pk1;
        }
        // ---- issue prefetch for next row (hidden behind stages B+C) ----
        if (hh + 1 < NITER) {
            const int hN = h0 + hh + 1;
            const float* Xl = Xb + (size_t)hN * (WW * DD);
            const int*   Yl = Yb + (size_t)ys * (size_t)hN * (WW * DD);
            if (hasA0) { pk0 = Yl[off0 * ys]; pv0 = Xl[off0 + pk0 * CHST]; }
            if (hasA1) { pk1 = Yl[off1 * ys]; pv1 = Xl[off1 + pk1 * CHST]; }
        }
        __syncthreads();

        // ---- Stage B: D-window-7, paired (2 outputs share 6-tap core) ----
        for (int j = tid; j < nB; j += TPB) {
            int wl = j / 23;
            int de = (j - wl * 23) * 2;
            int base = wl * DIN + de;
            __half2 A01 = hz, A23 = hz, B01 = hz, B23 = hz;
            unsigned n = 0u;
            #pragma unroll
            for (int t7 = 1; t7 < 7; ++t7) {
                uint4 u = eab[base + t7];
                A01 = __hadd2(A01, u2h(u.x)); A23 = __hadd2(A23, u2h(u.y));
                B01 = __hadd2(B01, u2h(u.z)); B23 = __hadd2(B23, u2h(u.w));
                n += 1u << (en[base + t7] * 8);
            }
            uint4 u0v = eab[base];
            uint4 u7v = eab[base + 7];
            unsigned n0 = 1u << (en[base] * 8);
            unsigned n7 = 1u << (en[base + 7] * 8);
            int o = wl * DLN + de;
            lsAB[o]   = make_uint4(h2u(__hadd2(A01, u2h(u0v.x))), h2u(__hadd2(A23, u2h(u0v.y))),
                                   h2u(__hadd2(B01, u2h(u0v.z))), h2u(__hadd2(B23, u2h(u0v.w))));
            lsN[o]    = n + n0;
            lsAB[o+1] = make_uint4(h2u(__hadd2(A01, u2h(u7v.x))), h2u(__hadd2(A23, u2h(u7v.y))),
                                   h2u(__hadd2(B01, u2h(u7v.z))), h2u(__hadd2(B23, u2h(u7v.w))));
            lsN[o+1]  = n + n7;
        }
        __syncthreads();

        // ---- Stage C: W-window-7 + sliding-H update + finalize ----
        if (tid < P) {
            __half2 A01 = hz, A23 = hz, B01 = hz, B23 = hz;
            unsigned n = 0u;
            #pragma unroll
            for (int j7 = 0; j7 < 7; ++j7) {
                int q = (pw + j7) * DLN + lidx;
                uint4 u = lsAB[q];
                A01 = __hadd2(A01, u2h(u.x)); A23 = __hadd2(A23, u2h(u.y));
                B01 = __hadd2(B01, u2h(u.z)); B23 = __hadd2(B23, u2h(u.w));
                n += lsN[q];
            }
            float2 fa01 = __half22float2(A01), fa23 = __half22float2(A23);
            float2 fb01 = __half22float2(B01), fb23 = __half22float2(B23);

            aA.x += fa01.x; aA.y += fa01.y; aA.z += fa23.x; aA.w += fa23.y;
            aB.x += fb01.x; aB.y += fb01.y; aB.z += fb23.x; aB.w += fb23.y;
            s02 += n & 0x00FF00FFu;
            s13 += (n >> 8) & 0x00FF00FFu;

            int rp = (hh % 7) * PMAX + tid;
            if (hh >= 7) {
                uint4 oldv = rAB[rp];
                unsigned on = rN[rp];
                float2 c01 = __half22float2(u2h(oldv.x)), c23 = __half22float2(u2h(oldv.y));
                float2 d01 = __half22float2(u2h(oldv.z)), d23 = __half22float2(u2h(oldv.w));
                aA.x -= c01.x; aA.y -= c01.y; aA.z -= c23.x; aA.w -= c23.y;
                aB.x -= d01.x; aB.y -= d01.y; aB.z -= d23.x; aB.w -= d23.y;
                s02 -= on & 0x00FF00FFu;
                s13 -= (on >> 8) & 0x00FF00FFu;
            }
            rAB[rp] = make_uint4(h2u(A01), h2u(A23), h2u(B01), h2u(B23));
            rN[rp] = n;

            if (hh >= 6) {
                float N0 = (float)(s02 & 0xFFFFu);
                float N2 = (float)(s02 >> 16);
                float N1 = (float)(s13 & 0xFFFFu);
                float N3 = (float)(s13 >> 16);
                float n0, d0c, n1, d1, n2, d2, n3, d3;
                nd_class(aA.x, aB.x, N0, n0, d0c);
                nd_class(aA.y, aB.y, N1, n1, d1);
                nd_class(aA.z, aB.z, N2, n2, d2);
                nd_class(aA.w, aB.w, N3, n3, d3);
                float p01 = d0c * d1, p23 = d2 * d3;
                float num = fmaf(n0, d1, n1 * d0c) * p23 + fmaf(n2, d3, n3 * d2) * p01;
                lsum += __fdividef(num, p01 * p23);
            }
        }
        __syncthreads();
    }

    // ---- block reduce + global accumulate + last-block finalize ----
    float* red = (float*)sm;
    red[tid] = lsum;
    __syncthreads();
    if (tid < 128) red[tid] += red[tid + 128] + red[tid + 256];
    __syncthreads();
    if (tid < 64) red[tid] += red[tid + 64];
    __syncthreads();
    if (tid < 32) {
        float v = red[tid] + red[tid + 32];
        #pragma unroll
        for (int o = 16; o > 0; o >>= 1)
            v += __shfl_down_sync(0xffffffffu, v, o);
        if (tid == 0) {
            atomicAdd(&g_acc, (double)v);
            __threadfence();
            unsigned t = atomicAdd(&g_done, 1u);
            if (t == TOTB - 1) {
                double tot = g_acc;
                out[0] = (float)(1.0 - tot * (1.0 / 17075520.0));
                __threadfence();
                g_acc = 0.0;
                g_done = 0u;
            }
        }
    }
}

extern "C" void kernel_launch(void* const* d_in, const int* in_sizes, int n_in,
                              void* d_out, int out_size)
{
    (void)out_size;
    const float* X;
    const int*   Y;
    if (n_in >= 2 && in_sizes[0] == Y_ELEMS) {
        Y = (const int*)d_in[0];
        X = (const float*)d_in[1];
    } else {
        X = (const float*)d_in[0];
        Y = (const int*)d_in[1];
    }

    static int smem_set = 0;
    if (!smem_set) {
        cudaFuncSetAttribute(kf, cudaFuncAttributeMaxDynamicSharedMemorySize, SMEMF);
        smem_set = 1;
    }

    kf<<<dim3(NWCH, NHSEG, BB * 2), TPB, SMEMF>>>(X, Y, (float*)d_out);
}